// round 4
// baseline (speedup 1.0000x reference)
#include <cuda_runtime.h>
#include <cstdint>

// Problem constants (AxCoreDSEWLinear): y[16,8192] = x @ (W * scale_grp)^T + bias
#define BATCH 16
#define INF   8192
#define OUTF  8192
#define NG    64          // scale groups along in_features
#define GRP   128         // group size
#define KC    1024        // k-chunk held in smem (double buffered)
#define NCHUNK (INF / KC) // 8
#define GPC    (KC / GRP) // 8 groups per chunk
#define THREADS 256
#define WARPS   8
#define RPW     4                       // output rows per warp
#define ROWS_PER_BLOCK (WARPS * RPW)    // 32
#define NBLOCKS (OUTF / ROWS_PER_BLOCK) // 256
#define SMEM_BYTES ((2 * BATCH * KC + ROWS_PER_BLOCK * NG) * 4) // 139264

// ---- packed f32x2 helpers (Blackwell FFMA2 path, PTX-only) ----
__device__ __forceinline__ unsigned long long fma2(unsigned long long a,
                                                   unsigned long long b,
                                                   unsigned long long c) {
    unsigned long long d;
    asm("fma.rn.f32x2 %0, %1, %2, %3;" : "=l"(d) : "l"(a), "l"(b), "l"(c));
    return d;
}
__device__ __forceinline__ unsigned long long mul2(unsigned long long a,
                                                   unsigned long long b) {
    unsigned long long d;
    asm("mul.rn.f32x2 %0, %1, %2;" : "=l"(d) : "l"(a), "l"(b));
    return d;
}
__device__ __forceinline__ unsigned long long pack2(float lo, float hi) {
    unsigned long long d;
    asm("mov.b64 %0, {%1, %2};" : "=l"(d) : "f"(lo), "f"(hi));
    return d;
}
__device__ __forceinline__ float2 unpack2(unsigned long long v) {
    float2 r;
    asm("mov.b64 {%0, %1}, %2;" : "=f"(r.x), "=f"(r.y) : "l"(v));
    return r;
}
__device__ __forceinline__ void cp16(uint32_t dst_smem, const void* src) {
    asm volatile("cp.async.cg.shared.global [%0], [%1], 16;"
                 :: "r"(dst_smem), "l"(src));
}

extern __shared__ float smem[];

__global__ void __launch_bounds__(THREADS, 1)
dsew_linear_kernel(const float* __restrict__ x,
                   const float* __restrict__ w,
                   const float* __restrict__ scale,
                   const float* __restrict__ bias,
                   float* __restrict__ out)
{
    float* xs = smem;                      // [2][BATCH][KC]
    float* ss = smem + 2 * BATCH * KC;     // [ROWS_PER_BLOCK * NG]

    const int tid  = threadIdx.x;
    const int warp = tid >> 5;
    const int lane = tid & 31;
    const int row_base = blockIdx.x * ROWS_PER_BLOCK;

    // stage this block's scales (contiguous 2048 floats)
    for (int i = tid; i < ROWS_PER_BLOCK * NG; i += THREADS)
        ss[i] = scale[(size_t)row_base * NG + i];

    const uint32_t xs_base = (uint32_t)__cvta_generic_to_shared(xs);

    // --- async-load chunk 0 into buffer 0 ---
    {
        #pragma unroll
        for (int i = 0; i < (BATCH * KC / 4) / THREADS; ++i) { // 16 iters
            int f = tid + i * THREADS;
            int b = f >> 8;       // KC/4 = 256 16B-units per row
            int j = f & 255;
            cp16(xs_base + (uint32_t)((b * KC + j * 4) * 4),
                 x + (size_t)b * INF + j * 4);
        }
        asm volatile("cp.async.commit_group;");
    }

    // per-warp output rows + accumulators
    const int r0 = row_base + warp * RPW;
    const float* wp0 = w + (size_t)r0 * INF;

    unsigned long long acc[RPW][BATCH];
    #pragma unroll
    for (int r = 0; r < RPW; ++r)
        #pragma unroll
        for (int b = 0; b < BATCH; ++b) acc[r][b] = 0ull;

    // prefetch W for group 0 (overlaps the cp.async x load)
    ulonglong2 wv[RPW];
    {
        const float* wp = wp0 + lane * 4;
        #pragma unroll
        for (int r = 0; r < RPW; ++r)
            wv[r] = *(const ulonglong2*)(wp + (size_t)r * INF);
    }

    asm volatile("cp.async.wait_group 0;");
    __syncthreads();

    for (int c = 0; c < NCHUNK; ++c) {
        // issue next x chunk into the other buffer (overlaps compute below)
        if (c + 1 < NCHUNK) {
            const int cn = c + 1;
            const uint32_t dbase = xs_base + (uint32_t)(((cn & 1) * BATCH * KC) * 4);
            #pragma unroll
            for (int i = 0; i < 16; ++i) {
                int f = tid + i * THREADS;
                int b = f >> 8;
                int j = f & 255;
                cp16(dbase + (uint32_t)((b * KC + j * 4) * 4),
                     x + (size_t)b * INF + (size_t)cn * KC + j * 4);
            }
        }
        asm volatile("cp.async.commit_group;");

        const float* xbuf = xs + (c & 1) * BATCH * KC;

        #pragma unroll 1
        for (int gl = 0; gl < GPC; ++gl) {
            const int g = c * GPC + gl;

            // prefetch next group's W (rolling register double-buffer)
            ulonglong2 wnext[RPW];
            {
                const int gnext = (g + 1 < NG) ? g + 1 : g;
                const float* wpn = wp0 + (size_t)gnext * GRP + lane * 4;
                #pragma unroll
                for (int r = 0; r < RPW; ++r)
                    wnext[r] = *(const ulonglong2*)(wpn + (size_t)r * INF);
            }

            // fold per-(row,group) scale into the 4 W values per row
            unsigned long long wsa[RPW], wsb[RPW];
            #pragma unroll
            for (int r = 0; r < RPW; ++r) {
                float s = ss[(warp * RPW + r) * NG + g];
                unsigned long long s2 = pack2(s, s);
                wsa[r] = mul2(wv[r].x, s2);
                wsb[r] = mul2(wv[r].y, s2);
            }

            const float* xp = xbuf + gl * GRP + lane * 4;
            #pragma unroll
            for (int b = 0; b < BATCH; ++b) {
                ulonglong2 xv = *(const ulonglong2*)(xp + (size_t)b * KC);
                #pragma unroll
                for (int r = 0; r < RPW; ++r) {
                    acc[r][b] = fma2(xv.x, wsa[r], acc[r][b]);
                    acc[r][b] = fma2(xv.y, wsb[r], acc[r][b]);
                }
            }

            #pragma unroll
            for (int r = 0; r < RPW; ++r) wv[r] = wnext[r];
        }

        asm volatile("cp.async.wait_group 0;");
        __syncthreads();
    }

    // ---- epilogue: fold k-parity pair, warp-reduce over 32 lanes, + bias ----
    #pragma unroll
    for (int r = 0; r < RPW; ++r) {
        const int row = r0 + r;
        const float bi = bias[row];
        #pragma unroll
        for (int b = 0; b < BATCH; ++b) {
            float2 p = unpack2(acc[r][b]);
            float v = p.x + p.y;
            #pragma unroll
            for (int off = 16; off; off >>= 1)
                v += __shfl_xor_sync(0xffffffffu, v, off);
            if (lane == 0)
                out[(size_t)b * OUTF + row] = v + bi;
        }
    }
}

extern "C" void kernel_launch(void* const* d_in, const int* in_sizes, int n_in,
                              void* d_out, int out_size)
{
    const float* x     = (const float*)d_in[0]; // [16, 8192]
    const float* wgt   = (const float*)d_in[1]; // [8192, 8192]
    const float* scale = (const float*)d_in[2]; // [8192, 64]
    const float* bias  = (const float*)d_in[3]; // [1, 8192]
    // d_in[4] (types) is a no-op in the reference math.
    float* out = (float*)d_out;                 // [16, 8192]

    cudaFuncSetAttribute(dsew_linear_kernel,
                         cudaFuncAttributeMaxDynamicSharedMemorySize, SMEM_BYTES);
    dsew_linear_kernel<<<NBLOCKS, THREADS, SMEM_BYTES>>>(x, wgt, scale, bias, out);
}

// round 5
// speedup vs baseline: 1.2332x; 1.2332x over previous
#include <cuda_runtime.h>
#include <cstdint>

// y[16,8192] = x[16,8192] @ (W[8192,8192] * scale[o, k/128])^T + bias
#define BATCH 16
#define INF   8192
#define OUTF  8192
#define NG    64
#define GRP   128
#define KC    512                 // k per smem chunk
#define NCHUNK (INF / KC)         // 16
#define GPC    (KC / GRP)         // 4 groups per chunk
#define THREADS 256
#define WARPS   8
#define RPW     4
#define ROWS_PER_BLOCK (WARPS * RPW)    // 32
#define NBLOCKS (OUTF / ROWS_PER_BLOCK) // 256
// x buffer: [2][GPC][16 units][32 lanes][4 floats] = 2*8192 floats; + scales
#define XBUF_FLOATS (BATCH * KC)        // 8192
#define SMEM_BYTES ((2 * XBUF_FLOATS + ROWS_PER_BLOCK * NG) * 4)  // 73728

__device__ __forceinline__ unsigned long long fma2(unsigned long long a,
                                                   unsigned long long b,
                                                   unsigned long long c) {
    unsigned long long d;
    asm("fma.rn.f32x2 %0, %1, %2, %3;" : "=l"(d) : "l"(a), "l"(b), "l"(c));
    return d;
}
__device__ __forceinline__ unsigned long long add2(unsigned long long a,
                                                   unsigned long long b) {
    unsigned long long d;
    asm("add.rn.f32x2 %0, %1, %2;" : "=l"(d) : "l"(a), "l"(b));
    return d;
}
__device__ __forceinline__ unsigned long long pack2(float lo, float hi) {
    unsigned long long d;
    asm("mov.b64 %0, {%1, %2};" : "=l"(d) : "f"(lo), "f"(hi));
    return d;
}
__device__ __forceinline__ float2 unpack2(unsigned long long v) {
    float2 r;
    asm("mov.b64 {%0, %1}, %2;" : "=f"(r.x), "=f"(r.y) : "l"(v));
    return r;
}

extern __shared__ float smem[];

// Stage one KC-chunk of x into smem, TRANSPOSED into:
//   buf[group][unit(i*4+u)][lane][4 floats]   (unit 16B = batches 4u..4u+3 at k)
// where, within a group of 128 k: lane = k/4, i = k%4.
// Reader (compute) lane L then fetches its x as 16 lane-consecutive LDS.128.
__device__ __forceinline__ void stage_x(float* buf, const float* __restrict__ x,
                                        int chunk, int tid)
{
    #pragma unroll
    for (int j = 0; j < (2 * XBUF_FLOATS / 16) / THREADS / 2; ++j) { /* placeholder */ }
    #pragma unroll
    for (int j = 0; j < 8; ++j) {               // 2048 16B-units / 256 threads
        int uid  = j * THREADS + tid;
        int g    = uid >> 9;                    // group within chunk
        int rem  = uid & 511;
        int u    = rem >> 7;                    // batch quad
        int kloc = rem & 127;                   // k within group (coalesced over tid)
        const float* xp = x + (size_t)chunk * KC + (size_t)g * GRP + kloc;
        float4 v;
        v.x = xp[(size_t)(4 * u + 0) * INF];
        v.y = xp[(size_t)(4 * u + 1) * INF];
        v.z = xp[(size_t)(4 * u + 2) * INF];
        v.w = xp[(size_t)(4 * u + 3) * INF];
        float* dst = buf + g * 2048 + ((kloc & 3) * 4 + u) * 128 + (kloc >> 2) * 4;
        *(float4*)dst = v;
    }
}

__global__ void __launch_bounds__(THREADS, 2)
dsew_linear_kernel(const float* __restrict__ x,
                   const float* __restrict__ w,
                   const float* __restrict__ scale,
                   const float* __restrict__ bias,
                   float* __restrict__ out)
{
    float* xs = smem;                       // [2][XBUF_FLOATS]
    float* ss = smem + 2 * XBUF_FLOATS;     // [ROWS_PER_BLOCK * NG]

    const int tid  = threadIdx.x;
    const int warp = tid >> 5;
    const int lane = tid & 31;
    const int row_base = blockIdx.x * ROWS_PER_BLOCK;

    for (int i = tid; i < ROWS_PER_BLOCK * NG; i += THREADS)
        ss[i] = scale[(size_t)row_base * NG + i];

    const int r0 = row_base + warp * RPW;
    const float* wp0 = w + (size_t)r0 * INF + lane * 4;  // lane's 16B within a group

    // batch-pair-packed accumulators: acc[r][p] holds (batch 2p, batch 2p+1)
    unsigned long long acc[RPW][8];
    #pragma unroll
    for (int r = 0; r < RPW; ++r)
        #pragma unroll
        for (int p = 0; p < 8; ++p) acc[r][p] = 0ull;

    // W register double-buffer (raw, unscaled), ping-pong on group parity
    float4 wbuf[2][RPW];
    #pragma unroll
    for (int r = 0; r < RPW; ++r)
        wbuf[0][r] = *(const float4*)(wp0 + (size_t)r * INF);

    stage_x(xs, x, 0, tid);
    __syncthreads();

    for (int c = 0; c < NCHUNK; ++c) {
        if (c + 1 < NCHUNK)
            stage_x(xs + ((c + 1) & 1) * XBUF_FLOATS, x, c + 1, tid);

        const float* xbuf = xs + (c & 1) * XBUF_FLOATS;

        #pragma unroll
        for (int gl = 0; gl < GPC; ++gl) {
            const int g = c * GPC + gl;

            // prefetch next group's W into the other ping-pong slot
            {
                const int gn = (g + 1 < NG) ? g + 1 : g;
                const float* wpn = wp0 + (size_t)gn * GRP;
                #pragma unroll
                for (int r = 0; r < RPW; ++r)
                    wbuf[(gl + 1) & 1][r] = *(const float4*)(wpn + (size_t)r * INF);
            }

            const float4* wcur = wbuf[gl & 1];
            float s[RPW];
            #pragma unroll
            for (int r = 0; r < RPW; ++r)
                s[r] = ss[(warp * RPW + r) * NG + g];

            const float* xg = xbuf + gl * 2048 + lane * 4;

            #pragma unroll
            for (int i = 0; i < 4; ++i) {
                // scale-fold + duplicate W scalar into both f32x2 halves
                unsigned long long w2[RPW];
                #pragma unroll
                for (int r = 0; r < RPW; ++r) {
                    float f = ((const float*)&wcur[r])[i] * s[r];
                    w2[r] = pack2(f, f);
                }
                #pragma unroll
                for (int u = 0; u < 4; ++u) {
                    ulonglong2 xv = *(const ulonglong2*)(xg + (i * 4 + u) * 128);
                    #pragma unroll
                    for (int r = 0; r < RPW; ++r) {
                        acc[r][2 * u]     = fma2(xv.x, w2[r], acc[r][2 * u]);
                        acc[r][2 * u + 1] = fma2(xv.y, w2[r], acc[r][2 * u + 1]);
                    }
                }
            }
        }
        __syncthreads();
    }

    // epilogue: reduce each f32x2 accumulator across the 32 k-lanes
    #pragma unroll
    for (int r = 0; r < RPW; ++r) {
        const int row = r0 + r;
        const float bi = bias[row];
        #pragma unroll
        for (int p = 0; p < 8; ++p) {
            unsigned long long v = acc[r][p];
            #pragma unroll
            for (int off = 16; off; off >>= 1)
                v = add2(v, __shfl_xor_sync(0xffffffffu, v, off));
            if (lane == 0) {
                float2 f = unpack2(v);
                out[(size_t)(2 * p)     * OUTF + row] = f.x + bi;
                out[(size_t)(2 * p + 1) * OUTF + row] = f.y + bi;
            }
        }
    }
}

extern "C" void kernel_launch(void* const* d_in, const int* in_sizes, int n_in,
                              void* d_out, int out_size)
{
    const float* x     = (const float*)d_in[0]; // [16, 8192]
    const float* wgt   = (const float*)d_in[1]; // [8192, 8192]
    const float* scale = (const float*)d_in[2]; // [8192, 64]
    const float* bias  = (const float*)d_in[3]; // [1, 8192]
    // d_in[4] (types) is a constant lookup with no effect on the math.
    float* out = (float*)d_out;                 // [16, 8192]

    cudaFuncSetAttribute(dsew_linear_kernel,
                         cudaFuncAttributeMaxDynamicSharedMemorySize, SMEM_BYTES);
    dsew_linear_kernel<<<NBLOCKS, THREADS, SMEM_BYTES>>>(x, wgt, scale, bias, out);
}